// round 13
// baseline (speedup 1.0000x reference)
#include <cuda_runtime.h>
#include <cuda_bf16.h>
#include <cuda_fp16.h>
#include <cstdint>

// ---------------------------------------------------------------------------
// EarlyFusionGRU: two biGRUs (B=256, T=512, H=128) + fusion MLP + 2 heads.
// Backward direction contributes only hb_seq[0] = ONE GRU step from h0=0 on
// x[:, T-1]. R13: warp-specialized fused kernel — warps 0-11 run the serial
// h-recurrence MMAs (critical path), warps 12-15 compute the x-projection
// (Wi@x) one step AHEAD into a double-buffered gate-preact buffer, so the
// projection runs entirely in the shadow of the recurrence.
// ---------------------------------------------------------------------------

#define B 256
#define T 512
#define H 128
#define G3 384   // 3*H
#define BPITCH 136   // half pitch of the h B-tile rows

static __device__ float d_hcat[(size_t)B * 512];      // [hg_f | hg_b | ha_f | ha_b]

__device__ __forceinline__ float sigmoidf_(float x) { return 1.0f / (1.0f + expf(-x)); }
__device__ __forceinline__ float tanh_ap(float x) {
    float y; asm("tanh.approx.f32 %0, %1;" : "=f"(y) : "f"(x)); return y;
}
__device__ __forceinline__ float sig_ap(float x) {
    return fmaf(tanh_ap(0.5f * x), 0.5f, 0.5f);
}
__device__ __forceinline__ uint32_t pkh2(float a, float b) {
    __half2 h = __floats2half2_rn(a, b);
    return *(uint32_t*)&h;
}
__device__ __forceinline__ void mma16816(float* c, const uint32_t* a, uint32_t b0, uint32_t b1) {
    asm volatile(
        "mma.sync.aligned.m16n8k16.row.col.f32.f16.f16.f32 "
        "{%0,%1,%2,%3}, {%4,%5,%6,%7}, {%8,%9}, {%0,%1,%2,%3};"
        : "+f"(c[0]), "+f"(c[1]), "+f"(c[2]), "+f"(c[3])
        : "r"(a[0]), "r"(a[1]), "r"(a[2]), "r"(a[3]), "r"(b0), "r"(b1));
}
__device__ __forceinline__ uint32_t smem_u32(const void* p) {
    uint32_t a; asm("{ .reg .u64 t; cvta.to.shared.u64 t, %1; cvt.u32.u64 %0, t; }" : "=r"(a) : "l"(p));
    return a;
}
__device__ __forceinline__ void cpasync4(uint32_t dst, const void* src) {
    asm volatile("cp.async.ca.shared.global [%0], [%1], 4;" :: "r"(dst), "l"(src));
}
#define CP_COMMIT() asm volatile("cp.async.commit_group;" ::: "memory")
#define CP_WAIT1()  asm volatile("cp.async.wait_group 1;" ::: "memory")
#define CP_WAIT0()  asm volatile("cp.async.wait_group 0;" ::: "memory")
#define BAR_PROJ()  asm volatile("bar.sync 1, 128;" ::: "memory")

// ---- fused recurrence + look-ahead projection on HMMA ----------------------
__global__ __launch_bounds__(512, 1) void rec_fused_kernel(
    const float* __restrict__ g_x, const float* __restrict__ a_x,
    const float* __restrict__ g_wif, const float* __restrict__ g_bif,
    const float* __restrict__ g_whf, const float* __restrict__ g_bhf,
    const float* __restrict__ a_wif, const float* __restrict__ a_bif,
    const float* __restrict__ a_whf, const float* __restrict__ a_bhf) {
    int net = blockIdx.y;
    int b0 = blockIdx.x * 8;
    const float* x  = net ? a_x : g_x;
    int I           = net ? 64 : 63;
    const float* Wi = net ? a_wif : g_wif;
    const float* bi = net ? a_bif : g_bif;
    const float* Wh = net ? a_whf : g_whf;
    const float* bh = net ? a_bhf : g_bhf;

    int tid = threadIdx.x;
    int wid = tid >> 5;
    int lane = tid & 31;
    int qr = lane >> 2;
    int qc = lane & 3;

    // smem layout
    extern __shared__ char dynsm[];
    __half (*Bh)[BPITCH] = (__half(*)[BPITCH])dynsm;                 // 2176 -> 2304
    __half (*Bx)[8][72]  = (__half(*)[8][72])(dynsm + 2304);         // 2304
    float (*Dsh)[10]     = (float(*)[10])(dynsm + 4608);             // 15360
    float (*xg)[384][10] = (float(*)[384][10])(dynsm + 19968);       // 30720
    float* slab          = (float*)(dynsm + 50688);                  // 4096
    uint4* XFs           = (uint4*)(dynsm + 54784);                  // 24576
    uint32_t slab_u32 = smem_u32(slab);

    // ---- fragment setup -----------------------------------------------------
    uint32_t A[2][8][4];     // MMA warps: Wh fragments (64 regs)
    uint32_t AXr[3][4][4];   // proj warps: Wi fragments for m-tiles 0-2 (48 regs)
    if (wid < 12) {
#pragma unroll
        for (int mt = 0; mt < 2; mt++) {
            int R = (wid * 2 + mt) * 16;
            int r0 = R + qr, r1 = r0 + 8;
            const float2* w0p = (const float2*)(Wh + (size_t)r0 * 128);
            const float2* w1p = (const float2*)(Wh + (size_t)r1 * 128);
#pragma unroll
            for (int kb = 0; kb < 8; kb++) {
                int ci = kb * 8 + qc;
                float2 e00 = w0p[ci], e10 = w1p[ci];
                float2 e01 = w0p[ci + 4], e11 = w1p[ci + 4];
                A[mt][kb][0] = pkh2(e00.x, e00.y);
                A[mt][kb][1] = pkh2(e10.x, e10.y);
                A[mt][kb][2] = pkh2(e01.x, e01.y);
                A[mt][kb][3] = pkh2(e11.x, e11.y);
            }
        }
    } else {
        int pw = wid - 12;           // 0..3
        int pt = tid - 384;          // 0..127
#pragma unroll
        for (int mt6 = 0; mt6 < 6; mt6++) {
            int R = (pw * 6 + mt6) * 16;
            int r0 = R + qr, r1 = r0 + 8;
#pragma unroll
            for (int kx = 0; kx < 4; kx++) {
                int k0 = kx * 16 + qc * 2;
                uint32_t f[4];
#pragma unroll
                for (int r = 0; r < 2; r++) {
                    int ka = k0 + r * 8, kb2 = ka + 1;
                    float wa0 = (ka < I) ? Wi[(size_t)r0 * I + ka] : 0.0f;
                    float wa1 = (kb2 < I) ? Wi[(size_t)r0 * I + kb2] : 0.0f;
                    float wb0 = (ka < I) ? Wi[(size_t)r1 * I + ka] : 0.0f;
                    float wb1 = (kb2 < I) ? Wi[(size_t)r1 * I + kb2] : 0.0f;
                    f[0 + r * 2] = pkh2(wa0, wa1);
                    f[1 + r * 2] = pkh2(wb0, wb1);
                }
                if (mt6 < 3) {
                    AXr[mt6][kx][0] = f[0]; AXr[mt6][kx][1] = f[1];
                    AXr[mt6][kx][2] = f[2]; AXr[mt6][kx][3] = f[3];
                } else {
                    XFs[((mt6 - 3) * 4 + kx) * 128 + pt] = make_uint4(f[0], f[1], f[2], f[3]);
                }
            }
        }
    }

    // zero B-tiles (h0 = 0; Bx padding columns stay zero forever)
    for (int i = tid; i < 8 * BPITCH; i += 512)
        ((__half*)Bh)[i] = __float2half_rn(0.0f);
    for (int i = tid; i < 2 * 8 * 72; i += 512)
        ((__half*)Bx)[i] = __float2half_rn(0.0f);

    // activation bookkeeping
    int bL = tid >> 7;            // 0..3
    int jj = tid & 127;
    float brz_r = bi[jj] + bh[jj];
    float brz_z = bi[128 + jj] + bh[128 + jj];
    float bin   = bi[256 + jj];
    float bhn   = bh[256 + jj];

    float h0v = 0.0f, h1v = 0.0f;
    __syncthreads();   // frags + zeroed tiles visible

    // ---- proj-warp prologue: slab(0), slab(1); Bx[0]; xg[0] -----------------
    if (wid >= 12) {
        int pt = tid - 384;
#pragma unroll 1
        for (int tt = 0; tt < 2; tt++) {
            for (int i = pt; i < 512; i += 128) {
                int b = i >> 6, k = i & 63;
                if (k < I)
                    cpasync4(slab_u32 + (tt * 512 + i) * 4,
                             x + (size_t)(b0 + b) * (T * I) + (size_t)tt * I + k);
            }
            CP_COMMIT();
        }
        CP_WAIT1();   // slab(0) resident
        for (int i = pt; i < 512; i += 128) {
            int b = i >> 6, k = i & 63;
            if (k < I) Bx[0][b][k] = __float2half_rn(slab[i]);
        }
        BAR_PROJ();
        // xg[0] = Wi @ x(0)
        int pw = wid - 12;
        const __half* BxF = &Bx[0][0][0];
#pragma unroll
        for (int mt6 = 0; mt6 < 6; mt6++) {
            float c[4] = {0.f, 0.f, 0.f, 0.f};
#pragma unroll
            for (int kx = 0; kx < 4; kx++) {
                int koff = qr * 72 + kx * 16 + qc * 2;
                uint32_t bf0 = *(const uint32_t*)(BxF + koff);
                uint32_t bf1 = *(const uint32_t*)(BxF + koff + 8);
                if (mt6 < 3) {
                    mma16816(c, AXr[mt6][kx], bf0, bf1);
                } else {
                    uint4 f = XFs[((mt6 - 3) * 4 + kx) * 128 + pt];
                    uint32_t af[4] = {f.x, f.y, f.z, f.w};
                    mma16816(c, af, bf0, bf1);
                }
            }
            int R = (pw * 6 + mt6) * 16;
            *(float2*)&xg[0][R + qr][2 * qc]     = make_float2(c[0], c[1]);
            *(float2*)&xg[0][R + qr + 8][2 * qc] = make_float2(c[2], c[3]);
        }
    }

    const __half* BhF = &Bh[0][0];

#pragma unroll 1
    for (int t = 0; t < T; t++) {
        if (wid < 12) {
            // ---- h-recurrence MMAs (critical path) --------------------------
            float c0[2][4], c1[2][4];
#pragma unroll
            for (int mt = 0; mt < 2; mt++)
#pragma unroll
                for (int r = 0; r < 4; r++) { c0[mt][r] = 0.0f; c1[mt][r] = 0.0f; }
#pragma unroll
            for (int kb = 0; kb < 8; kb += 2) {
                int koff = qr * BPITCH + kb * 16 + qc * 2;
                uint32_t bf0 = *(const uint32_t*)(BhF + koff);
                uint32_t bf1 = *(const uint32_t*)(BhF + koff + 8);
                uint32_t bf2 = *(const uint32_t*)(BhF + koff + 16);
                uint32_t bf3 = *(const uint32_t*)(BhF + koff + 24);
#pragma unroll
                for (int mt = 0; mt < 2; mt++) {
                    mma16816(c0[mt], A[mt][kb], bf0, bf1);
                    mma16816(c1[mt], A[mt][kb + 1], bf2, bf3);
                }
            }
#pragma unroll
            for (int mt = 0; mt < 2; mt++) {
                int R = (wid * 2 + mt) * 16;
                *(float2*)&Dsh[R + qr][2 * qc] =
                    make_float2(c0[mt][0] + c1[mt][0], c0[mt][1] + c1[mt][1]);
                *(float2*)&Dsh[R + qr + 8][2 * qc] =
                    make_float2(c0[mt][2] + c1[mt][2], c0[mt][3] + c1[mt][3]);
            }
        } else {
            // ---- look-ahead projection (one step ahead) ---------------------
            int pt = tid - 384;
            int pw = wid - 12;
            int nb = (t + 1) & 1;
            CP_WAIT0();   // slab(t+1) resident
            for (int i = pt; i < 512; i += 128) {
                int b = i >> 6, k = i & 63;
                if (k < I) Bx[nb][b][k] = __float2half_rn(slab[nb * 512 + i]);
            }
            BAR_PROJ();
            const __half* BxF = &Bx[nb][0][0];
#pragma unroll
            for (int mt6 = 0; mt6 < 6; mt6++) {
                float c[4] = {0.f, 0.f, 0.f, 0.f};
#pragma unroll
                for (int kx = 0; kx < 4; kx++) {
                    int koff = qr * 72 + kx * 16 + qc * 2;
                    uint32_t bf0 = *(const uint32_t*)(BxF + koff);
                    uint32_t bf1 = *(const uint32_t*)(BxF + koff + 8);
                    if (mt6 < 3) {
                        mma16816(c, AXr[mt6][kx], bf0, bf1);
                    } else {
                        uint4 f = XFs[((mt6 - 3) * 4 + kx) * 128 + pt];
                        uint32_t af[4] = {f.x, f.y, f.z, f.w};
                        mma16816(c, af, bf0, bf1);
                    }
                }
                int R = (pw * 6 + mt6) * 16;
                *(float2*)&xg[nb][R + qr][2 * qc]     = make_float2(c[0], c[1]);
                *(float2*)&xg[nb][R + qr + 8][2 * qc] = make_float2(c[2], c[3]);
            }
            // stage slab(t+2) into buffer (t+2)&1 == t&1
            int tn = (t + 2 < T) ? (t + 2) : (T - 1);
            uint32_t dst = slab_u32 + ((t & 1) * 512) * 4;
            for (int i = pt; i < 512; i += 128) {
                int b = i >> 6, k = i & 63;
                if (k < I)
                    cpasync4(dst + i * 4,
                             x + (size_t)(b0 + b) * (T * I) + (size_t)tn * I + k);
            }
            CP_COMMIT();
        }
        __syncthreads();   // A: Dsh + xg[t&1] ready

        // ---- activation: 2 (batch, jj) entries per thread -------------------
        const float (*xgc)[10] = xg[t & 1];
        {
            int bb = bL;
            float r = sig_ap(xgc[jj][bb] + Dsh[jj][bb] + brz_r);
            float z = sig_ap(xgc[128 + jj][bb] + Dsh[128 + jj][bb] + brz_z);
            float n = tanh_ap(xgc[256 + jj][bb] + bin + r * (Dsh[256 + jj][bb] + bhn));
            h0v = n + z * (h0v - n);
            Bh[bb][jj] = __float2half_rn(h0v);
        }
        {
            int bb = bL + 4;
            float r = sig_ap(xgc[jj][bb] + Dsh[jj][bb] + brz_r);
            float z = sig_ap(xgc[128 + jj][bb] + Dsh[128 + jj][bb] + brz_z);
            float n = tanh_ap(xgc[256 + jj][bb] + bin + r * (Dsh[256 + jj][bb] + bhn));
            h1v = n + z * (h1v - n);
            Bh[bb][jj] = __float2half_rn(h1v);
        }
        __syncthreads();   // B: Bh(t+1) ready
    }

    // write final forward h
    {
        int off = net ? 256 : 0;
        d_hcat[(size_t)(b0 + bL) * 512 + off + jj]     = h0v;
        d_hcat[(size_t)(b0 + bL + 4) * 512 + off + jj] = h1v;
    }
}

// ---- backward direction = ONE GRU step from h0=0 on x[:, T-1] --------------
__global__ __launch_bounds__(384) void bwd_kernel(
    const float* __restrict__ g_x, const float* __restrict__ a_x,
    const float* __restrict__ g_wib, const float* __restrict__ g_bib, const float* __restrict__ g_bhb,
    const float* __restrict__ a_wib, const float* __restrict__ a_bib, const float* __restrict__ a_bhb) {
    int bb0 = blockIdx.x * 8;
    int net = blockIdx.y;
    const float* x  = net ? a_x : g_x;
    int I           = net ? 64 : 63;
    const float* Wi = net ? a_wib : g_wib;
    const float* bi = net ? a_bib : g_bib;
    const float* bv = net ? a_bhb : g_bhb;

    __shared__ float xs[8][64];
    __shared__ float gsh[384][9];
    int j = threadIdx.x;  // 0..383

    for (int i = j; i < 512; i += 384) {
        int b = i >> 6, k = i & 63;
        xs[b][k] = (k < I) ? x[(size_t)(bb0 + b) * T * I + (size_t)(T - 1) * I + k] : 0.0f;
    }
    __syncthreads();

    {
        const float* wrow = Wi + (size_t)j * I;
        float acc[8];
        float bj = bi[j];
#pragma unroll
        for (int b = 0; b < 8; b++) acc[b] = bj;
        for (int k = 0; k < I; k++) {
            float w = wrow[k];
#pragma unroll
            for (int b = 0; b < 8; b++) acc[b] += w * xs[b][k];
        }
#pragma unroll
        for (int b = 0; b < 8; b++) gsh[j][b] = acc[b];
    }
    __syncthreads();

    if (j < 128) {
        int u = j;
        int off = net ? 256 : 0;
        float bvr = bv[u], bvz = bv[128 + u], bvn = bv[256 + u];
#pragma unroll
        for (int b = 0; b < 8; b++) {
            float r = sigmoidf_(gsh[u][b] + bvr);
            float z = sigmoidf_(gsh[128 + u][b] + bvz);
            float n = tanhf(gsh[256 + u][b] + r * bvn);
            d_hcat[(size_t)(bb0 + b) * 512 + off + 128 + u] = (1.0f - z) * n;
        }
    }
}

// ---- fusion MLP (512->256->128 relu) + heads (20, 30) ----------------------
__global__ __launch_bounds__(256) void mlp_kernel(
    const float* __restrict__ w1, const float* __restrict__ b1,
    const float* __restrict__ w2, const float* __restrict__ b2,
    const float* __restrict__ wm, const float* __restrict__ bm,
    const float* __restrict__ wa, const float* __restrict__ ba,
    float* __restrict__ out) {
    int b = blockIdx.x;
    __shared__ float hin[512];
    __shared__ float h1[256];
    __shared__ float h2[128];
    int t = threadIdx.x;
    hin[t]       = d_hcat[(size_t)b * 512 + t];
    hin[t + 256] = d_hcat[(size_t)b * 512 + 256 + t];
    __syncthreads();
    {
        float acc = b1[t];
        const float* wr = w1 + (size_t)t * 512;
#pragma unroll 8
        for (int k = 0; k < 512; k++) acc += wr[k] * hin[k];
        h1[t] = fmaxf(acc, 0.0f);
    }
    __syncthreads();
    if (t < 128) {
        float acc = b2[t];
        const float* wr = w2 + (size_t)t * 256;
#pragma unroll 8
        for (int k = 0; k < 256; k++) acc += wr[k] * h1[k];
        h2[t] = fmaxf(acc, 0.0f);
    }
    __syncthreads();
    if (t < 20) {
        float acc = bm[t];
        const float* wr = wm + (size_t)t * 128;
#pragma unroll 8
        for (int k = 0; k < 128; k++) acc += wr[k] * h2[k];
        out[(size_t)b * 20 + t] = acc;                       // lm
    } else if (t < 50) {
        int q = t - 20;
        float acc = ba[q];
        const float* wr = wa + (size_t)q * 128;
#pragma unroll 8
        for (int k = 0; k < 128; k++) acc += wr[k] * h2[k];
        out[5120 + (size_t)b * 30 + q] = acc;                // la (after 256*20 lm)
    }
}

extern "C" void kernel_launch(void* const* d_in, const int* in_sizes, int n_in,
                              void* d_out, int out_size) {
    const float* g_seq  = (const float*)d_in[0];
    const float* a_seq  = (const float*)d_in[1];
    const float* g_wif  = (const float*)d_in[2];
    const float* g_whf  = (const float*)d_in[3];
    const float* g_bif  = (const float*)d_in[4];
    const float* g_bhf  = (const float*)d_in[5];
    const float* g_wib  = (const float*)d_in[6];
    const float* g_bib  = (const float*)d_in[8];
    const float* g_bhb  = (const float*)d_in[9];
    const float* a_wif  = (const float*)d_in[10];
    const float* a_whf  = (const float*)d_in[11];
    const float* a_bif  = (const float*)d_in[12];
    const float* a_bhf  = (const float*)d_in[13];
    const float* a_wib  = (const float*)d_in[14];
    const float* a_bib  = (const float*)d_in[16];
    const float* a_bhb  = (const float*)d_in[17];
    const float* fuse_w1 = (const float*)d_in[18];
    const float* fuse_b1 = (const float*)d_in[19];
    const float* fuse_w2 = (const float*)d_in[20];
    const float* fuse_b2 = (const float*)d_in[21];
    const float* wm = (const float*)d_in[22];
    const float* bm = (const float*)d_in[23];
    const float* wa = (const float*)d_in[24];
    const float* ba = (const float*)d_in[25];

    const int rec_smem = 2304 + 2304 + 15360 + 30720 + 4096 + 24576;  // 79360
    cudaFuncSetAttribute(rec_fused_kernel, cudaFuncAttributeMaxDynamicSharedMemorySize, rec_smem);

    bwd_kernel<<<dim3(B / 8, 2), 384>>>(g_seq, a_seq, g_wib, g_bib, g_bhb, a_wib, a_bib, a_bhb);
    rec_fused_kernel<<<dim3(B / 8, 2), 512, rec_smem>>>(
        g_seq, a_seq, g_wif, g_bif, g_whf, g_bhf, a_wif, a_bif, a_whf, a_bhf);
    mlp_kernel<<<B, 256>>>(fuse_w1, fuse_b1, fuse_w2, fuse_b2, wm, bm, wa, ba, (float*)d_out);
}

// round 14
// speedup vs baseline: 1.2201x; 1.2201x over previous
#include <cuda_runtime.h>
#include <cuda_bf16.h>
#include <cuda_fp16.h>
#include <cstdint>

// ---------------------------------------------------------------------------
// EarlyFusionGRU: two biGRUs (B=256, T=512, H=128) + fusion MLP + 2 heads.
// Backward direction contributes only hb_seq[0] = ONE GRU step from h0=0 on
// x[:, T-1]. R14: warp-specialized fused kernel with the R13 register-liveness
// bug fixed — proj warps keep ALL Wi fragments in SMEM private slots, so the
// only loop-live register fragment array is the Wh one (no spills).
// Warps 0-11: serial h-recurrence MMAs (critical path).
// Warps 12-15: x-projection one step ahead (cp.async + 24 MMAs), shadowed.
// ---------------------------------------------------------------------------

#define B 256
#define T 512
#define H 128
#define G3 384   // 3*H
#define BPITCH 136   // half pitch of the h B-tile rows

static __device__ float d_hcat[(size_t)B * 512];      // [hg_f | hg_b | ha_f | ha_b]

__device__ __forceinline__ float sigmoidf_(float x) { return 1.0f / (1.0f + expf(-x)); }
__device__ __forceinline__ float tanh_ap(float x) {
    float y; asm("tanh.approx.f32 %0, %1;" : "=f"(y) : "f"(x)); return y;
}
__device__ __forceinline__ float sig_ap(float x) {
    return fmaf(tanh_ap(0.5f * x), 0.5f, 0.5f);
}
__device__ __forceinline__ uint32_t pkh2(float a, float b) {
    __half2 h = __floats2half2_rn(a, b);
    return *(uint32_t*)&h;
}
__device__ __forceinline__ void mma16816(float* c, const uint32_t* a, uint32_t b0, uint32_t b1) {
    asm volatile(
        "mma.sync.aligned.m16n8k16.row.col.f32.f16.f16.f32 "
        "{%0,%1,%2,%3}, {%4,%5,%6,%7}, {%8,%9}, {%0,%1,%2,%3};"
        : "+f"(c[0]), "+f"(c[1]), "+f"(c[2]), "+f"(c[3])
        : "r"(a[0]), "r"(a[1]), "r"(a[2]), "r"(a[3]), "r"(b0), "r"(b1));
}
__device__ __forceinline__ uint32_t smem_u32(const void* p) {
    uint32_t a; asm("{ .reg .u64 t; cvta.to.shared.u64 t, %1; cvt.u32.u64 %0, t; }" : "=r"(a) : "l"(p));
    return a;
}
__device__ __forceinline__ void cpasync4(uint32_t dst, const void* src) {
    asm volatile("cp.async.ca.shared.global [%0], [%1], 4;" :: "r"(dst), "l"(src));
}
#define CP_COMMIT() asm volatile("cp.async.commit_group;" ::: "memory")
#define CP_WAIT1()  asm volatile("cp.async.wait_group 1;" ::: "memory")
#define CP_WAIT0()  asm volatile("cp.async.wait_group 0;" ::: "memory")
#define BAR_PROJ()  asm volatile("bar.sync 1, 128;" ::: "memory")

// ---- fused recurrence + look-ahead projection on HMMA ----------------------
__global__ __launch_bounds__(512, 1) void rec_fused_kernel(
    const float* __restrict__ g_x, const float* __restrict__ a_x,
    const float* __restrict__ g_wif, const float* __restrict__ g_bif,
    const float* __restrict__ g_whf, const float* __restrict__ g_bhf,
    const float* __restrict__ a_wif, const float* __restrict__ a_bif,
    const float* __restrict__ a_whf, const float* __restrict__ a_bhf) {
    int net = blockIdx.y;
    int b0 = blockIdx.x * 8;
    const float* x  = net ? a_x : g_x;
    int I           = net ? 64 : 63;
    const float* Wi = net ? a_wif : g_wif;
    const float* bi = net ? a_bif : g_bif;
    const float* Wh = net ? a_whf : g_whf;
    const float* bh = net ? a_bhf : g_bhf;

    int tid = threadIdx.x;
    int wid = tid >> 5;
    int lane = tid & 31;
    int qr = lane >> 2;
    int qc = lane & 3;

    // smem layout
    extern __shared__ char dynsm[];
    __half (*Bh)[BPITCH] = (__half(*)[BPITCH])dynsm;                 // 2176 -> 2304
    __half (*Bx)[8][72]  = (__half(*)[8][72])(dynsm + 2304);         // 2304
    float (*Dsh)[10]     = (float(*)[10])(dynsm + 4608);             // 15360
    float (*xg)[384][10] = (float(*)[384][10])(dynsm + 19968);       // 30720
    float* slab          = (float*)(dynsm + 50688);                  // 4096
    uint4* XFs           = (uint4*)(dynsm + 54784);                  // 49152 (24 quads x 128)
    uint32_t slab_u32 = smem_u32(slab);

    // ---- fragment setup -----------------------------------------------------
    // The ONLY loop-live register fragment array (64 regs). Proj warps keep all
    // Wi fragments in SMEM private slots (no second live array -> no spills).
    uint32_t A[2][8][4];
    if (wid < 12) {
#pragma unroll
        for (int mt = 0; mt < 2; mt++) {
            int R = (wid * 2 + mt) * 16;
            int r0 = R + qr, r1 = r0 + 8;
            const float2* w0p = (const float2*)(Wh + (size_t)r0 * 128);
            const float2* w1p = (const float2*)(Wh + (size_t)r1 * 128);
#pragma unroll
            for (int kb = 0; kb < 8; kb++) {
                int ci = kb * 8 + qc;
                float2 e00 = w0p[ci], e10 = w1p[ci];
                float2 e01 = w0p[ci + 4], e11 = w1p[ci + 4];
                A[mt][kb][0] = pkh2(e00.x, e00.y);
                A[mt][kb][1] = pkh2(e10.x, e10.y);
                A[mt][kb][2] = pkh2(e01.x, e01.y);
                A[mt][kb][3] = pkh2(e11.x, e11.y);
            }
        }
    } else {
        int pw = wid - 12;           // 0..3
        int pt = tid - 384;          // 0..127
#pragma unroll
        for (int mt6 = 0; mt6 < 6; mt6++) {
            int R = (pw * 6 + mt6) * 16;
            int r0 = R + qr, r1 = r0 + 8;
#pragma unroll
            for (int kx = 0; kx < 4; kx++) {
                int k0 = kx * 16 + qc * 2;
                uint32_t f[4];
#pragma unroll
                for (int r = 0; r < 2; r++) {
                    int ka = k0 + r * 8, kb2 = ka + 1;
                    float wa0 = (ka < I) ? Wi[(size_t)r0 * I + ka] : 0.0f;
                    float wa1 = (kb2 < I) ? Wi[(size_t)r0 * I + kb2] : 0.0f;
                    float wb0 = (ka < I) ? Wi[(size_t)r1 * I + ka] : 0.0f;
                    float wb1 = (kb2 < I) ? Wi[(size_t)r1 * I + kb2] : 0.0f;
                    f[0 + r * 2] = pkh2(wa0, wa1);
                    f[1 + r * 2] = pkh2(wb0, wb1);
                }
                XFs[(mt6 * 4 + kx) * 128 + pt] = make_uint4(f[0], f[1], f[2], f[3]);
            }
        }
    }

    // zero B-tiles (h0 = 0; Bx padding columns stay zero forever)
    for (int i = tid; i < 8 * BPITCH; i += 512)
        ((__half*)Bh)[i] = __float2half_rn(0.0f);
    for (int i = tid; i < 2 * 8 * 72; i += 512)
        ((__half*)Bx)[i] = __float2half_rn(0.0f);

    // activation bookkeeping
    int bL = tid >> 7;            // 0..3
    int jj = tid & 127;
    float brz_r = bi[jj] + bh[jj];
    float brz_z = bi[128 + jj] + bh[128 + jj];
    float bin   = bi[256 + jj];
    float bhn   = bh[256 + jj];

    float h0v = 0.0f, h1v = 0.0f;
    __syncthreads();   // frags + zeroed tiles visible

    // ---- proj-warp prologue: slab(0), slab(1); Bx[0]; xg[0] -----------------
    if (wid >= 12) {
        int pt = tid - 384;
#pragma unroll 1
        for (int tt = 0; tt < 2; tt++) {
            for (int i = pt; i < 512; i += 128) {
                int b = i >> 6, k = i & 63;
                if (k < I)
                    cpasync4(slab_u32 + (tt * 512 + i) * 4,
                             x + (size_t)(b0 + b) * (T * I) + (size_t)tt * I + k);
            }
            CP_COMMIT();
        }
        CP_WAIT1();   // slab(0) resident
        for (int i = pt; i < 512; i += 128) {
            int b = i >> 6, k = i & 63;
            if (k < I) Bx[0][b][k] = __float2half_rn(slab[i]);
        }
        BAR_PROJ();
        // xg[0] = Wi @ x(0)
        int pw = wid - 12;
        const __half* BxF = &Bx[0][0][0];
#pragma unroll
        for (int mt6 = 0; mt6 < 6; mt6++) {
            float c[4] = {0.f, 0.f, 0.f, 0.f};
#pragma unroll
            for (int kx = 0; kx < 4; kx++) {
                int koff = qr * 72 + kx * 16 + qc * 2;
                uint32_t bf0 = *(const uint32_t*)(BxF + koff);
                uint32_t bf1 = *(const uint32_t*)(BxF + koff + 8);
                uint4 f = XFs[(mt6 * 4 + kx) * 128 + pt];
                uint32_t af[4] = {f.x, f.y, f.z, f.w};
                mma16816(c, af, bf0, bf1);
            }
            int R = (pw * 6 + mt6) * 16;
            *(float2*)&xg[0][R + qr][2 * qc]     = make_float2(c[0], c[1]);
            *(float2*)&xg[0][R + qr + 8][2 * qc] = make_float2(c[2], c[3]);
        }
    }

    const __half* BhF = &Bh[0][0];

#pragma unroll 1
    for (int t = 0; t < T; t++) {
        if (wid < 12) {
            // ---- h-recurrence MMAs (critical path) --------------------------
            float c0[2][4], c1[2][4];
#pragma unroll
            for (int mt = 0; mt < 2; mt++)
#pragma unroll
                for (int r = 0; r < 4; r++) { c0[mt][r] = 0.0f; c1[mt][r] = 0.0f; }
#pragma unroll
            for (int kb = 0; kb < 8; kb += 2) {
                int koff = qr * BPITCH + kb * 16 + qc * 2;
                uint32_t bf0 = *(const uint32_t*)(BhF + koff);
                uint32_t bf1 = *(const uint32_t*)(BhF + koff + 8);
                uint32_t bf2 = *(const uint32_t*)(BhF + koff + 16);
                uint32_t bf3 = *(const uint32_t*)(BhF + koff + 24);
#pragma unroll
                for (int mt = 0; mt < 2; mt++) {
                    mma16816(c0[mt], A[mt][kb], bf0, bf1);
                    mma16816(c1[mt], A[mt][kb + 1], bf2, bf3);
                }
            }
#pragma unroll
            for (int mt = 0; mt < 2; mt++) {
                int R = (wid * 2 + mt) * 16;
                *(float2*)&Dsh[R + qr][2 * qc] =
                    make_float2(c0[mt][0] + c1[mt][0], c0[mt][1] + c1[mt][1]);
                *(float2*)&Dsh[R + qr + 8][2 * qc] =
                    make_float2(c0[mt][2] + c1[mt][2], c0[mt][3] + c1[mt][3]);
            }
        } else {
            // ---- look-ahead projection (one step ahead) ---------------------
            int pt = tid - 384;
            int pw = wid - 12;
            int nb = (t + 1) & 1;
            CP_WAIT0();   // slab(t+1) resident (committed one full step ago)
            for (int i = pt; i < 512; i += 128) {
                int b = i >> 6, k = i & 63;
                if (k < I) Bx[nb][b][k] = __float2half_rn(slab[nb * 512 + i]);
            }
            BAR_PROJ();
            const __half* BxF = &Bx[nb][0][0];
#pragma unroll
            for (int mt6 = 0; mt6 < 6; mt6++) {
                float c[4] = {0.f, 0.f, 0.f, 0.f};
#pragma unroll
                for (int kx = 0; kx < 4; kx++) {
                    int koff = qr * 72 + kx * 16 + qc * 2;
                    uint32_t bf0 = *(const uint32_t*)(BxF + koff);
                    uint32_t bf1 = *(const uint32_t*)(BxF + koff + 8);
                    uint4 f = XFs[(mt6 * 4 + kx) * 128 + pt];
                    uint32_t af[4] = {f.x, f.y, f.z, f.w};
                    mma16816(c, af, bf0, bf1);
                }
                int R = (pw * 6 + mt6) * 16;
                *(float2*)&xg[nb][R + qr][2 * qc]     = make_float2(c[0], c[1]);
                *(float2*)&xg[nb][R + qr + 8][2 * qc] = make_float2(c[2], c[3]);
            }
            // stage slab(t+2) into buffer (t+2)&1 == t&1
            int tn = (t + 2 < T) ? (t + 2) : (T - 1);
            uint32_t dst = slab_u32 + ((t & 1) * 512) * 4;
            for (int i = pt; i < 512; i += 128) {
                int b = i >> 6, k = i & 63;
                if (k < I)
                    cpasync4(dst + i * 4,
                             x + (size_t)(b0 + b) * (T * I) + (size_t)tn * I + k);
            }
            CP_COMMIT();
        }
        __syncthreads();   // A: Dsh + xg[t&1] ready

        // ---- activation: 2 (batch, jj) entries per thread -------------------
        const float (*xgc)[10] = xg[t & 1];
        {
            int bb = bL;
            float r = sig_ap(xgc[jj][bb] + Dsh[jj][bb] + brz_r);
            float z = sig_ap(xgc[128 + jj][bb] + Dsh[128 + jj][bb] + brz_z);
            float n = tanh_ap(xgc[256 + jj][bb] + bin + r * (Dsh[256 + jj][bb] + bhn));
            h0v = n + z * (h0v - n);
            Bh[bb][jj] = __float2half_rn(h0v);
        }
        {
            int bb = bL + 4;
            float r = sig_ap(xgc[jj][bb] + Dsh[jj][bb] + brz_r);
            float z = sig_ap(xgc[128 + jj][bb] + Dsh[128 + jj][bb] + brz_z);
            float n = tanh_ap(xgc[256 + jj][bb] + bin + r * (Dsh[256 + jj][bb] + bhn));
            h1v = n + z * (h1v - n);
            Bh[bb][jj] = __float2half_rn(h1v);
        }
        __syncthreads();   // B: Bh(t+1) ready
    }

    // write final forward h
    {
        int off = net ? 256 : 0;
        d_hcat[(size_t)(b0 + bL) * 512 + off + jj]     = h0v;
        d_hcat[(size_t)(b0 + bL + 4) * 512 + off + jj] = h1v;
    }
}

// ---- backward direction = ONE GRU step from h0=0 on x[:, T-1] --------------
__global__ __launch_bounds__(384) void bwd_kernel(
    const float* __restrict__ g_x, const float* __restrict__ a_x,
    const float* __restrict__ g_wib, const float* __restrict__ g_bib, const float* __restrict__ g_bhb,
    const float* __restrict__ a_wib, const float* __restrict__ a_bib, const float* __restrict__ a_bhb) {
    int bb0 = blockIdx.x * 8;
    int net = blockIdx.y;
    const float* x  = net ? a_x : g_x;
    int I           = net ? 64 : 63;
    const float* Wi = net ? a_wib : g_wib;
    const float* bi = net ? a_bib : g_bib;
    const float* bv = net ? a_bhb : g_bhb;

    __shared__ float xs[8][64];
    __shared__ float gsh[384][9];
    int j = threadIdx.x;  // 0..383

    for (int i = j; i < 512; i += 384) {
        int b = i >> 6, k = i & 63;
        xs[b][k] = (k < I) ? x[(size_t)(bb0 + b) * T * I + (size_t)(T - 1) * I + k] : 0.0f;
    }
    __syncthreads();

    {
        const float* wrow = Wi + (size_t)j * I;
        float acc[8];
        float bj = bi[j];
#pragma unroll
        for (int b = 0; b < 8; b++) acc[b] = bj;
        for (int k = 0; k < I; k++) {
            float w = wrow[k];
#pragma unroll
            for (int b = 0; b < 8; b++) acc[b] += w * xs[b][k];
        }
#pragma unroll
        for (int b = 0; b < 8; b++) gsh[j][b] = acc[b];
    }
    __syncthreads();

    if (j < 128) {
        int u = j;
        int off = net ? 256 : 0;
        float bvr = bv[u], bvz = bv[128 + u], bvn = bv[256 + u];
#pragma unroll
        for (int b = 0; b < 8; b++) {
            float r = sigmoidf_(gsh[u][b] + bvr);
            float z = sigmoidf_(gsh[128 + u][b] + bvz);
            float n = tanhf(gsh[256 + u][b] + r * bvn);
            d_hcat[(size_t)(bb0 + b) * 512 + off + 128 + u] = (1.0f - z) * n;
        }
    }
}

// ---- fusion MLP (512->256->128 relu) + heads (20, 30) ----------------------
__global__ __launch_bounds__(256) void mlp_kernel(
    const float* __restrict__ w1, const float* __restrict__ b1,
    const float* __restrict__ w2, const float* __restrict__ b2,
    const float* __restrict__ wm, const float* __restrict__ bm,
    const float* __restrict__ wa, const float* __restrict__ ba,
    float* __restrict__ out) {
    int b = blockIdx.x;
    __shared__ float hin[512];
    __shared__ float h1[256];
    __shared__ float h2[128];
    int t = threadIdx.x;
    hin[t]       = d_hcat[(size_t)b * 512 + t];
    hin[t + 256] = d_hcat[(size_t)b * 512 + 256 + t];
    __syncthreads();
    {
        float acc = b1[t];
        const float* wr = w1 + (size_t)t * 512;
#pragma unroll 8
        for (int k = 0; k < 512; k++) acc += wr[k] * hin[k];
        h1[t] = fmaxf(acc, 0.0f);
    }
    __syncthreads();
    if (t < 128) {
        float acc = b2[t];
        const float* wr = w2 + (size_t)t * 256;
#pragma unroll 8
        for (int k = 0; k < 256; k++) acc += wr[k] * h1[k];
        h2[t] = fmaxf(acc, 0.0f);
    }
    __syncthreads();
    if (t < 20) {
        float acc = bm[t];
        const float* wr = wm + (size_t)t * 128;
#pragma unroll 8
        for (int k = 0; k < 128; k++) acc += wr[k] * h2[k];
        out[(size_t)b * 20 + t] = acc;                       // lm
    } else if (t < 50) {
        int q = t - 20;
        float acc = ba[q];
        const float* wr = wa + (size_t)q * 128;
#pragma unroll 8
        for (int k = 0; k < 128; k++) acc += wr[k] * h2[k];
        out[5120 + (size_t)b * 30 + q] = acc;                // la (after 256*20 lm)
    }
}

extern "C" void kernel_launch(void* const* d_in, const int* in_sizes, int n_in,
                              void* d_out, int out_size) {
    const float* g_seq  = (const float*)d_in[0];
    const float* a_seq  = (const float*)d_in[1];
    const float* g_wif  = (const float*)d_in[2];
    const float* g_whf  = (const float*)d_in[3];
    const float* g_bif  = (const float*)d_in[4];
    const float* g_bhf  = (const float*)d_in[5];
    const float* g_wib  = (const float*)d_in[6];
    const float* g_bib  = (const float*)d_in[8];
    const float* g_bhb  = (const float*)d_in[9];
    const float* a_wif  = (const float*)d_in[10];
    const float* a_whf  = (const float*)d_in[11];
    const float* a_bif  = (const float*)d_in[12];
    const float* a_bhf  = (const float*)d_in[13];
    const float* a_wib  = (const float*)d_in[14];
    const float* a_bib  = (const float*)d_in[16];
    const float* a_bhb  = (const float*)d_in[17];
    const float* fuse_w1 = (const float*)d_in[18];
    const float* fuse_b1 = (const float*)d_in[19];
    const float* fuse_w2 = (const float*)d_in[20];
    const float* fuse_b2 = (const float*)d_in[21];
    const float* wm = (const float*)d_in[22];
    const float* bm = (const float*)d_in[23];
    const float* wa = (const float*)d_in[24];
    const float* ba = (const float*)d_in[25];

    const int rec_smem = 2304 + 2304 + 15360 + 30720 + 4096 + 49152;  // 103936
    cudaFuncSetAttribute(rec_fused_kernel, cudaFuncAttributeMaxDynamicSharedMemorySize, rec_smem);

    bwd_kernel<<<dim3(B / 8, 2), 384>>>(g_seq, a_seq, g_wib, g_bib, g_bhb, a_wib, a_bib, a_bhb);
    rec_fused_kernel<<<dim3(B / 8, 2), 512, rec_smem>>>(
        g_seq, a_seq, g_wif, g_bif, g_whf, g_bhf, a_wif, a_bif, a_whf, a_bhf);
    mlp_kernel<<<B, 256>>>(fuse_w1, fuse_b1, fuse_w2, fuse_b2, wm, bm, wa, ba, (float*)d_out);
}

// round 15
// speedup vs baseline: 1.8465x; 1.5134x over previous
#include <cuda_runtime.h>
#include <cuda_bf16.h>
#include <cuda_fp16.h>
#include <cstdint>

// ---------------------------------------------------------------------------
// EarlyFusionGRU: two biGRUs (B=256, T=512, H=128) + fusion MLP + 2 heads.
// Backward direction contributes only hb_seq[0] = ONE GRU step from h0=0 on
// x[:, T-1]. R15: R12 structure (known-good fused kernel, Wi frags in SMEM
// private slots) with 4 batches per CTA -> 128 CTAs: per-SM tensor work
// unchanged, per-step activation/exchange halved, 128/148 SMs busy.
// ---------------------------------------------------------------------------

#define B 256
#define T 512
#define H 128
#define G3 384   // 3*H
#define BPITCH 200   // B-tile row pitch (h cols 0-127, x cols 128-191)
#define NB 4         // batches per CTA

static __device__ float d_hcat[(size_t)B * 512];      // [hg_f | hg_b | ha_f | ha_b]

__device__ __forceinline__ float sigmoidf_(float x) { return 1.0f / (1.0f + expf(-x)); }
__device__ __forceinline__ float tanh_ap(float x) {
    float y; asm("tanh.approx.f32 %0, %1;" : "=f"(y) : "f"(x)); return y;
}
__device__ __forceinline__ float sig_ap(float x) {
    return fmaf(tanh_ap(0.5f * x), 0.5f, 0.5f);
}
__device__ __forceinline__ uint32_t pkh2(float a, float b) {
    __half2 h = __floats2half2_rn(a, b);
    return *(uint32_t*)&h;
}
__device__ __forceinline__ void mma16816(float* c, const uint32_t* a, uint32_t b0, uint32_t b1) {
    asm volatile(
        "mma.sync.aligned.m16n8k16.row.col.f32.f16.f16.f32 "
        "{%0,%1,%2,%3}, {%4,%5,%6,%7}, {%8,%9}, {%0,%1,%2,%3};"
        : "+f"(c[0]), "+f"(c[1]), "+f"(c[2]), "+f"(c[3])
        : "r"(a[0]), "r"(a[1]), "r"(a[2]), "r"(a[3]), "r"(b0), "r"(b1));
}
__device__ __forceinline__ uint32_t smem_u32(const void* p) {
    uint32_t a; asm("{ .reg .u64 t; cvta.to.shared.u64 t, %1; cvt.u32.u64 %0, t; }" : "=r"(a) : "l"(p));
    return a;
}
__device__ __forceinline__ void cpasync4(uint32_t dst, const void* src) {
    asm volatile("cp.async.ca.shared.global [%0], [%1], 4;" :: "r"(dst), "l"(src));
}
#define CP_COMMIT() asm volatile("cp.async.commit_group;" ::: "memory")
#define CP_WAIT1()  asm volatile("cp.async.wait_group 1;" ::: "memory")

// ---- fused projection + recurrence on HMMA (R12 structure, NB=4) -----------
// 512 threads: warps 0-11 MMA (2 m16-tiles each over 384 gate rows; K = 128 h
// + 64 x), warps 12-15 cp.async-stage raw x slabs (2-step pipeline).
// Wh fragments register-resident (64 regs); Wi fragments in SMEM private
// slots. B-tile rows 4-7 stay zero (n=8 padding for NB=4 real batches).
__global__ __launch_bounds__(512, 1) void rec_fused_kernel(
    const float* __restrict__ g_x, const float* __restrict__ a_x,
    const float* __restrict__ g_wif, const float* __restrict__ g_bif,
    const float* __restrict__ g_whf, const float* __restrict__ g_bhf,
    const float* __restrict__ a_wif, const float* __restrict__ a_bif,
    const float* __restrict__ a_whf, const float* __restrict__ a_bhf) {
    int net = blockIdx.y;
    int b0 = blockIdx.x * NB;
    const float* x  = net ? a_x : g_x;
    int I           = net ? 64 : 63;
    const float* Wi = net ? a_wif : g_wif;
    const float* bi = net ? a_bif : g_bif;
    const float* Wh = net ? a_whf : g_whf;
    const float* bh = net ? a_bhf : g_bhf;

    int tid = threadIdx.x;
    int wid = tid >> 5;
    int lane = tid & 31;
    int qr = lane >> 2;
    int qc = lane & 3;

    // smem: Bh | Dsh | Dxn | slab x2 | XF (x-fragments, [8][384] uint4)
    extern __shared__ char dynsm[];
    __half (*Bh)[BPITCH] = (__half(*)[BPITCH])dynsm;            // 3200 B (pad 3328)
    float (*Dsh)[10] = (float(*)[10])(dynsm + 3328);            // 15360 B
    float (*Dxn)[10] = (float(*)[10])(dynsm + 3328 + 15360);    // 5120 B
    float* slab = (float*)(dynsm + 3328 + 15360 + 5120);        // 2048 B
    uint4* XFs = (uint4*)(dynsm + 3328 + 15360 + 5120 + 2048);  // 49152 B
    uint32_t slab_u32 = smem_u32(slab);

    // ---- Wh fragments in registers (the only loop-live frag array) ----------
    uint32_t A[2][8][4];
    if (wid < 12) {
#pragma unroll
        for (int mt = 0; mt < 2; mt++) {
            int R = (wid * 2 + mt) * 16;
            int r0 = R + qr, r1 = r0 + 8;
            const float2* w0p = (const float2*)(Wh + (size_t)r0 * 128);
            const float2* w1p = (const float2*)(Wh + (size_t)r1 * 128);
#pragma unroll
            for (int kb = 0; kb < 8; kb++) {
                int ci = kb * 8 + qc;
                float2 e00 = w0p[ci], e10 = w1p[ci];
                float2 e01 = w0p[ci + 4], e11 = w1p[ci + 4];
                A[mt][kb][0] = pkh2(e00.x, e00.y);
                A[mt][kb][1] = pkh2(e10.x, e10.y);
                A[mt][kb][2] = pkh2(e01.x, e01.y);
                A[mt][kb][3] = pkh2(e11.x, e11.y);
            }
            // Wi fragments -> SMEM private slots (row-major [j][I], guard k>=I)
#pragma unroll
            for (int kx = 0; kx < 4; kx++) {
                int k0 = kx * 16 + qc * 2;
                uint32_t f[4];
#pragma unroll
                for (int r = 0; r < 2; r++) {
                    int ka = k0 + r * 8, kb2 = ka + 1;
                    float wa0 = (ka < I) ? Wi[(size_t)r0 * I + ka] : 0.0f;
                    float wa1 = (kb2 < I) ? Wi[(size_t)r0 * I + kb2] : 0.0f;
                    float wb0 = (ka < I) ? Wi[(size_t)r1 * I + ka] : 0.0f;
                    float wb1 = (kb2 < I) ? Wi[(size_t)r1 * I + kb2] : 0.0f;
                    f[0 + r * 2] = pkh2(wa0, wa1);
                    f[1 + r * 2] = pkh2(wb0, wb1);
                }
                XFs[(mt * 4 + kx) * 384 + tid] = make_uint4(f[0], f[1], f[2], f[3]);
            }
        }
    }

    // zero B-tile (h0 = 0; rows NB..7 stay zero forever)
    for (int i = tid; i < 8 * BPITCH; i += 512)
        ((__half*)Bh)[i] = __float2half_rn(0.0f);

    // activation bookkeeping: thread owns exactly one (bL, jj) entry
    int bL = tid >> 7;            // 0..3
    int jj = tid & 127;
    float brz_r = bi[jj] + bh[jj];
    float brz_z = bi[128 + jj] + bh[128 + jj];
    float bin   = bi[256 + jj];
    float bhn   = bh[256 + jj];

    // conversion mapping: threads < 256 -> one x element (b = tid>>6, k = tid&63)
    int cb = (tid >> 6) & 3, ck = tid & 63;

    float h0v = 0.0f;

    // prologue: stage slabs for t=0 and t=1 (NB*64 = 256 floats each)
    if (wid >= 12) {
        int ct = tid - 384;
#pragma unroll 1
        for (int tt = 0; tt < 2; tt++) {
            for (int i = ct; i < 256; i += 128) {
                int b = i >> 6, k = i & 63;
                if (k < I)
                    cpasync4(slab_u32 + (tt * 256 + i) * 4,
                             x + (size_t)(b0 + b) * (T * I) + (size_t)tt * I + k);
            }
            CP_COMMIT();
        }
        CP_WAIT1();   // t=0 slab resident
    }
    __syncthreads();
    // convert t=0 x into B-tile x region
    if (tid < 256) {
        float v = (ck < I) ? slab[cb * 64 + ck] : 0.0f;
        Bh[cb][128 + ck] = __float2half_rn(v);
    }
    __syncthreads();

    const __half* BhF = &Bh[0][0];

#pragma unroll 1
    for (int t = 0; t < T; t++) {
        if (wid >= 12) {
            // stage slab for t+2 into buffer (t+2)&1 == t&1
            int tn = (t + 2 < T) ? (t + 2) : (T - 1);
            int ct = tid - 384;
            uint32_t dst = slab_u32 + ((t & 1) * 256) * 4;
            for (int i = ct; i < 256; i += 128) {
                int b = i >> 6, k = i & 63;
                if (k < I)
                    cpasync4(dst + i * 4,
                             x + (size_t)(b0 + b) * (T * I) + (size_t)tn * I + k);
            }
            CP_COMMIT();
            CP_WAIT1();
        } else {
            // MMA phase
            float c0[2][4], c1[2][4];
#pragma unroll
            for (int mt = 0; mt < 2; mt++)
#pragma unroll
                for (int r = 0; r < 4; r++) { c0[mt][r] = 0.0f; c1[mt][r] = 0.0f; }

            if (wid < 8) {
                // r,z rows: x merged into the two chains
#pragma unroll
                for (int kb = 0; kb < 4; kb++) {
                    int koff = qr * BPITCH + kb * 16 + qc * 2;
                    uint32_t bf0 = *(const uint32_t*)(BhF + koff);
                    uint32_t bf1 = *(const uint32_t*)(BhF + koff + 8);
                    int koff2 = koff + 64;
                    uint32_t bg0 = *(const uint32_t*)(BhF + koff2);
                    uint32_t bg1 = *(const uint32_t*)(BhF + koff2 + 8);
#pragma unroll
                    for (int mt = 0; mt < 2; mt++) {
                        mma16816(c0[mt], A[mt][kb], bf0, bf1);
                        mma16816(c1[mt], A[mt][kb + 4], bg0, bg1);
                    }
                }
#pragma unroll
                for (int kx = 0; kx < 2; kx++) {
                    int koff = qr * BPITCH + 128 + kx * 16 + qc * 2;
                    uint32_t bf0 = *(const uint32_t*)(BhF + koff);
                    uint32_t bf1 = *(const uint32_t*)(BhF + koff + 8);
                    int koff2 = koff + 32;
                    uint32_t bg0 = *(const uint32_t*)(BhF + koff2);
                    uint32_t bg1 = *(const uint32_t*)(BhF + koff2 + 8);
#pragma unroll
                    for (int mt = 0; mt < 2; mt++) {
                        uint4 f = XFs[(mt * 4 + kx) * 384 + tid];
                        uint32_t af[4] = {f.x, f.y, f.z, f.w};
                        mma16816(c0[mt], af, bf0, bf1);
                        uint4 g = XFs[(mt * 4 + kx + 2) * 384 + tid];
                        uint32_t ag[4] = {g.x, g.y, g.z, g.w};
                        mma16816(c1[mt], ag, bg0, bg1);
                    }
                }
#pragma unroll
                for (int mt = 0; mt < 2; mt++) {
                    int R = (wid * 2 + mt) * 16;
                    *(float2*)&Dsh[R + qr][2 * qc] =
                        make_float2(c0[mt][0] + c1[mt][0], c0[mt][1] + c1[mt][1]);
                    *(float2*)&Dsh[R + qr + 8][2 * qc] =
                        make_float2(c0[mt][2] + c1[mt][2], c0[mt][3] + c1[mt][3]);
                }
            } else {
                // n rows: h in c0, x in c1 (kept separate)
#pragma unroll
                for (int kb = 0; kb < 8; kb++) {
                    int koff = qr * BPITCH + kb * 16 + qc * 2;
                    uint32_t bf0 = *(const uint32_t*)(BhF + koff);
                    uint32_t bf1 = *(const uint32_t*)(BhF + koff + 8);
#pragma unroll
                    for (int mt = 0; mt < 2; mt++)
                        mma16816(c0[mt], A[mt][kb], bf0, bf1);
                }
#pragma unroll
                for (int kx = 0; kx < 4; kx++) {
                    int koff = qr * BPITCH + 128 + kx * 16 + qc * 2;
                    uint32_t bf0 = *(const uint32_t*)(BhF + koff);
                    uint32_t bf1 = *(const uint32_t*)(BhF + koff + 8);
#pragma unroll
                    for (int mt = 0; mt < 2; mt++) {
                        uint4 f = XFs[(mt * 4 + kx) * 384 + tid];
                        uint32_t af[4] = {f.x, f.y, f.z, f.w};
                        mma16816(c1[mt], af, bf0, bf1);
                    }
                }
#pragma unroll
                for (int mt = 0; mt < 2; mt++) {
                    int R = (wid * 2 + mt) * 16;       // 256..383
                    *(float2*)&Dsh[R + qr][2 * qc] = make_float2(c0[mt][0], c0[mt][1]);
                    *(float2*)&Dsh[R + qr + 8][2 * qc] = make_float2(c0[mt][2], c0[mt][3]);
                    *(float2*)&Dxn[R - 256 + qr][2 * qc] = make_float2(c1[mt][0], c1[mt][1]);
                    *(float2*)&Dxn[R - 256 + qr + 8][2 * qc] = make_float2(c1[mt][2], c1[mt][3]);
                }
            }
        }
        __syncthreads();

        // activation: exactly one (batch, jj) entry per thread
        {
            int bb = bL;
            float r = sig_ap(Dsh[jj][bb] + brz_r);
            float z = sig_ap(Dsh[128 + jj][bb] + brz_z);
            float n = tanh_ap(Dxn[jj][bb] + bin + r * (Dsh[256 + jj][bb] + bhn));
            h0v = n + z * (h0v - n);
            Bh[bb][jj] = __float2half_rn(h0v);
        }
        // convert x for step t+1 into B-tile x region (slab (t+1)&1 resident)
        if (t + 1 < T && tid < 256) {
            float v = (ck < I) ? slab[((t + 1) & 1) * 256 + cb * 64 + ck] : 0.0f;
            Bh[cb][128 + ck] = __float2half_rn(v);
        }
        __syncthreads();
    }

    // write final forward h
    {
        int off = net ? 256 : 0;
        d_hcat[(size_t)(b0 + bL) * 512 + off + jj] = h0v;
    }
}

// ---- backward direction = ONE GRU step from h0=0 on x[:, T-1] --------------
__global__ __launch_bounds__(384) void bwd_kernel(
    const float* __restrict__ g_x, const float* __restrict__ a_x,
    const float* __restrict__ g_wib, const float* __restrict__ g_bib, const float* __restrict__ g_bhb,
    const float* __restrict__ a_wib, const float* __restrict__ a_bib, const float* __restrict__ a_bhb) {
    int bb0 = blockIdx.x * 8;
    int net = blockIdx.y;
    const float* x  = net ? a_x : g_x;
    int I           = net ? 64 : 63;
    const float* Wi = net ? a_wib : g_wib;
    const float* bi = net ? a_bib : g_bib;
    const float* bv = net ? a_bhb : g_bhb;

    __shared__ float xs[8][64];
    __shared__ float gsh[384][9];
    int j = threadIdx.x;  // 0..383

    for (int i = j; i < 512; i += 384) {
        int b = i >> 6, k = i & 63;
        xs[b][k] = (k < I) ? x[(size_t)(bb0 + b) * T * I + (size_t)(T - 1) * I + k] : 0.0f;
    }
    __syncthreads();

    {
        const float* wrow = Wi + (size_t)j * I;
        float acc[8];
        float bj = bi[j];
#pragma unroll
        for (int b = 0; b < 8; b++) acc[b] = bj;
        for (int k = 0; k < I; k++) {
            float w = wrow[k];
#pragma unroll
            for (int b = 0; b < 8; b++) acc[b] += w * xs[b][k];
        }
#pragma unroll
        for (int b = 0; b < 8; b++) gsh[j][b] = acc[b];
    }
    __syncthreads();

    if (j < 128) {
        int u = j;
        int off = net ? 256 : 0;
        float bvr = bv[u], bvz = bv[128 + u], bvn = bv[256 + u];
#pragma unroll
        for (int b = 0; b < 8; b++) {
            float r = sigmoidf_(gsh[u][b] + bvr);
            float z = sigmoidf_(gsh[128 + u][b] + bvz);
            float n = tanhf(gsh[256 + u][b] + r * bvn);
            d_hcat[(size_t)(bb0 + b) * 512 + off + 128 + u] = (1.0f - z) * n;
        }
    }
}

// ---- fusion MLP (512->256->128 relu) + heads (20, 30) ----------------------
__global__ __launch_bounds__(256) void mlp_kernel(
    const float* __restrict__ w1, const float* __restrict__ b1,
    const float* __restrict__ w2, const float* __restrict__ b2,
    const float* __restrict__ wm, const float* __restrict__ bm,
    const float* __restrict__ wa, const float* __restrict__ ba,
    float* __restrict__ out) {
    int b = blockIdx.x;
    __shared__ float hin[512];
    __shared__ float h1[256];
    __shared__ float h2[128];
    int t = threadIdx.x;
    hin[t]       = d_hcat[(size_t)b * 512 + t];
    hin[t + 256] = d_hcat[(size_t)b * 512 + 256 + t];
    __syncthreads();
    {
        float acc = b1[t];
        const float* wr = w1 + (size_t)t * 512;
#pragma unroll 8
        for (int k = 0; k < 512; k++) acc += wr[k] * hin[k];
        h1[t] = fmaxf(acc, 0.0f);
    }
    __syncthreads();
    if (t < 128) {
        float acc = b2[t];
        const float* wr = w2 + (size_t)t * 256;
#pragma unroll 8
        for (int k = 0; k < 256; k++) acc += wr[k] * h1[k];
        h2[t] = fmaxf(acc, 0.0f);
    }
    __syncthreads();
    if (t < 20) {
        float acc = bm[t];
        const float* wr = wm + (size_t)t * 128;
#pragma unroll 8
        for (int k = 0; k < 128; k++) acc += wr[k] * h2[k];
        out[(size_t)b * 20 + t] = acc;                       // lm
    } else if (t < 50) {
        int q = t - 20;
        float acc = ba[q];
        const float* wr = wa + (size_t)q * 128;
#pragma unroll 8
        for (int k = 0; k < 128; k++) acc += wr[k] * h2[k];
        out[5120 + (size_t)b * 30 + q] = acc;                // la (after 256*20 lm)
    }
}

extern "C" void kernel_launch(void* const* d_in, const int* in_sizes, int n_in,
                              void* d_out, int out_size) {
    const float* g_seq  = (const float*)d_in[0];
    const float* a_seq  = (const float*)d_in[1];
    const float* g_wif  = (const float*)d_in[2];
    const float* g_whf  = (const float*)d_in[3];
    const float* g_bif  = (const float*)d_in[4];
    const float* g_bhf  = (const float*)d_in[5];
    const float* g_wib  = (const float*)d_in[6];
    const float* g_bib  = (const float*)d_in[8];
    const float* g_bhb  = (const float*)d_in[9];
    const float* a_wif  = (const float*)d_in[10];
    const float* a_whf  = (const float*)d_in[11];
    const float* a_bif  = (const float*)d_in[12];
    const float* a_bhf  = (const float*)d_in[13];
    const float* a_wib  = (const float*)d_in[14];
    const float* a_bib  = (const float*)d_in[16];
    const float* a_bhb  = (const float*)d_in[17];
    const float* fuse_w1 = (const float*)d_in[18];
    const float* fuse_b1 = (const float*)d_in[19];
    const float* fuse_w2 = (const float*)d_in[20];
    const float* fuse_b2 = (const float*)d_in[21];
    const float* wm = (const float*)d_in[22];
    const float* bm = (const float*)d_in[23];
    const float* wa = (const float*)d_in[24];
    const float* ba = (const float*)d_in[25];

    const int rec_smem = 3328 + 15360 + 5120 + 2048 + 49152;  // Bh|Dsh|Dxn|slab|XF
    cudaFuncSetAttribute(rec_fused_kernel, cudaFuncAttributeMaxDynamicSharedMemorySize, rec_smem);

    bwd_kernel<<<dim3(B / 8, 2), 384>>>(g_seq, a_seq, g_wib, g_bib, g_bhb, a_wib, a_bib, a_bhb);
    rec_fused_kernel<<<dim3(B / NB, 2), 512, rec_smem>>>(
        g_seq, a_seq, g_wif, g_bif, g_whf, g_bhf, a_wif, a_bif, a_whf, a_bhf);
    mlp_kernel<<<B, 256>>>(fuse_w1, fuse_b1, fuse_w2, fuse_b2, wm, bm, wa, ba, (float*)d_out);
}